// round 16
// baseline (speedup 1.0000x reference)
#include <cuda_runtime.h>

// LIF scan over T=8 timesteps, N = 4,194,304 independent spatial elements.
//   mem = mem*0.25*(1-spike) + x[t]; spike = (mem >= 0.5)
// Pure streaming: 128 MiB read + 128 MiB write, zero reuse -> DRAM-bound.
//
// FINAL — 15-round sweep complete; kernel pinned at the balanced R/W HBM3e
// roofline (~5.9 TB/s sustained; ncu 36.2-36.9 us invariant across
// occupancy 32-84%, MLP 8/16, block 256/512, flat/persistent grids, all
// cache policies). Irreducible traffic: 256 MiB, fp32 output fixed by the
// harness. Binding facts: per-thread MLP must be >=8 (front-batched loads;
// interleaving cost +2.4 us ncu) and write-through stores regress.
// Winning shape (timed best 43.5 us, reproduced; owns all sub-43.8 results):
// flat one-float4-per-thread, 256-thread blocks, 8 front-batched __ldcs
// loads (MLP=8), __stcs stores (evict-first both ways; zero data reuse).

#define DECAY  0.25f
#define THRESH 0.5f

static constexpr int T = 8;

__global__ __launch_bounds__(256) void lif_scan_kernel(
    const float4* __restrict__ x, float4* __restrict__ out, int n4)
{
    int i = blockIdx.x * blockDim.x + threadIdx.x;
    if (i >= n4) return;

    // 8 independent streaming loads front-batched (MLP=8, evict-first).
    float4 xv[T];
#pragma unroll
    for (int t = 0; t < T; t++) {
        xv[t] = __ldcs(&x[(size_t)t * n4 + i]);
    }

    float4 mem   = make_float4(0.f, 0.f, 0.f, 0.f);
    float4 spike = make_float4(0.f, 0.f, 0.f, 0.f);

#pragma unroll
    for (int t = 0; t < T; t++) {
        mem.x = mem.x * (DECAY * (1.0f - spike.x)) + xv[t].x;
        mem.y = mem.y * (DECAY * (1.0f - spike.y)) + xv[t].y;
        mem.z = mem.z * (DECAY * (1.0f - spike.z)) + xv[t].z;
        mem.w = mem.w * (DECAY * (1.0f - spike.w)) + xv[t].w;
        spike.x = (mem.x >= THRESH) ? 1.0f : 0.0f;
        spike.y = (mem.y >= THRESH) ? 1.0f : 0.0f;
        spike.z = (mem.z >= THRESH) ? 1.0f : 0.0f;
        spike.w = (mem.w >= THRESH) ? 1.0f : 0.0f;
        __stcs(&out[(size_t)t * n4 + i], spike);
    }
}

extern "C" void kernel_launch(void* const* d_in, const int* in_sizes, int n_in,
                              void* d_out, int out_size)
{
    const float* x = (const float*)d_in[0];
    float* out = (float*)d_out;

    const int total = in_sizes[0];       // T * N
    const int n = total / T;             // elements per timestep (4,194,304)
    const int n4 = n / 4;                // float4 count per timestep (1,048,576)

    const int threads = 256;
    const int blocks = (n4 + threads - 1) / threads;  // 4096

    lif_scan_kernel<<<blocks, threads>>>(
        (const float4*)x, (float4*)out, n4);
}

// round 17
// speedup vs baseline: 1.0050x; 1.0050x over previous
#include <cuda_runtime.h>

// LIF scan over T=8 timesteps, N = 4,194,304 independent spatial elements.
//   mem = mem*0.25*(1-spike) + x[t]; spike = (mem >= 0.5)
// Pure streaming: 128 MiB read + 128 MiB write, zero reuse -> DRAM-bound.
//
// FINAL — 16-round sweep complete; kernel pinned at the balanced R/W HBM3e
// roofline (~5.9 TB/s sustained; ncu 36.2-37.3 us invariant across
// occupancy 32-84%, MLP 8/16, block 256/512, flat/persistent grids, all
// cache policies). Irreducible traffic: 256 MiB, fp32 output fixed by the
// harness. Binding facts: per-thread MLP must be >=8 (front-batched loads;
// interleaving cost +2.4 us ncu) and write-through stores regress.
// Winning shape (timed best 43.5 us, reproduced; owns all sub-43.8 results):
// flat one-float4-per-thread, 256-thread blocks, 8 front-batched __ldcs
// loads (MLP=8), __stcs stores (evict-first both ways; zero data reuse).

#define DECAY  0.25f
#define THRESH 0.5f

static constexpr int T = 8;

__global__ __launch_bounds__(256) void lif_scan_kernel(
    const float4* __restrict__ x, float4* __restrict__ out, int n4)
{
    int i = blockIdx.x * blockDim.x + threadIdx.x;
    if (i >= n4) return;

    // 8 independent streaming loads front-batched (MLP=8, evict-first).
    float4 xv[T];
#pragma unroll
    for (int t = 0; t < T; t++) {
        xv[t] = __ldcs(&x[(size_t)t * n4 + i]);
    }

    float4 mem   = make_float4(0.f, 0.f, 0.f, 0.f);
    float4 spike = make_float4(0.f, 0.f, 0.f, 0.f);

#pragma unroll
    for (int t = 0; t < T; t++) {
        mem.x = mem.x * (DECAY * (1.0f - spike.x)) + xv[t].x;
        mem.y = mem.y * (DECAY * (1.0f - spike.y)) + xv[t].y;
        mem.z = mem.z * (DECAY * (1.0f - spike.z)) + xv[t].z;
        mem.w = mem.w * (DECAY * (1.0f - spike.w)) + xv[t].w;
        spike.x = (mem.x >= THRESH) ? 1.0f : 0.0f;
        spike.y = (mem.y >= THRESH) ? 1.0f : 0.0f;
        spike.z = (mem.z >= THRESH) ? 1.0f : 0.0f;
        spike.w = (mem.w >= THRESH) ? 1.0f : 0.0f;
        __stcs(&out[(size_t)t * n4 + i], spike);
    }
}

extern "C" void kernel_launch(void* const* d_in, const int* in_sizes, int n_in,
                              void* d_out, int out_size)
{
    const float* x = (const float*)d_in[0];
    float* out = (float*)d_out;

    const int total = in_sizes[0];       // T * N
    const int n = total / T;             // elements per timestep (4,194,304)
    const int n4 = n / 4;                // float4 count per timestep (1,048,576)

    const int threads = 256;
    const int blocks = (n4 + threads - 1) / threads;  // 4096

    lif_scan_kernel<<<blocks, threads>>>(
        (const float4*)x, (float4*)out, n4);
}